// round 3
// baseline (speedup 1.0000x reference)
#include <cuda_runtime.h>
#include <math.h>

// Problem dims (fixed)
#define BB  64
#define NV  2048
#define NQ  512
#define HH  256
#define HA  128

// ---------------- scratch (device globals; no cudaMalloc allowed) ----------
__device__ float g_va[(size_t)BB * NV * HH];     // v @ Waff^T          128MB
__device__ float g_pv[(size_t)BB * NV * HA];     // v @ Wv^T + bv        64MB
__device__ float g_pq[(size_t)BB * NQ * HA];     // q @ Wq^T + bq        16MB
__device__ float g_aff[(size_t)BB * NQ * NV];    // tanh(q va^T)        256MB
__device__ float g_lv[BB * NV];                  // logits for a_v
__device__ float g_lq[BB * NQ];                  // logits for a_q

#define SMPAD 132   // 128 + 4 padding: kills staging-store bank conflicts

__device__ __forceinline__ float tanh_fast(float x) {
    // 1 - 2/(exp(2x)+1): 2 MUFU ops, abs err ~1e-6, saturates correctly at +-inf
    float e = __expf(2.0f * x);
    return 1.0f - __fdividef(2.0f, e + 1.0f);
}

// ============================================================================
// NT GEMM: C[M,N] = A[M,K] @ B[N,K]^T (+bias) (optional tanh)
// BM=BN=128, BK=16, 256 threads, 8x8 per thread, register-staged prefetch.
// M,N,K must be multiples of 128/128/16 (always true here).
// ============================================================================
template<int DO_TANH>
__global__ __launch_bounds__(256)
void gemm128_nt(const float* __restrict__ A, const float* __restrict__ Bm,
                const float* __restrict__ bias, float* __restrict__ C,
                int N, int K, long sA, long sB, long sC)
{
    const int b = blockIdx.z;
    A  += (long)b * sA;
    Bm += (long)b * sB;
    C  += (long)b * sC;

    __shared__ float As[16][SMPAD];
    __shared__ float Bs[16][SMPAD];

    const int tid = threadIdx.x;
    const int tx = tid & 15, ty = tid >> 4;
    const long m0 = (long)blockIdx.y * 128;
    const long n0 = (long)blockIdx.x * 128;

    const int lRow = tid >> 2;          // 0..63
    const int lCol = (tid & 3) << 2;    // 0,4,8,12

    const float* pA0 = A  + (m0 + lRow) * K + lCol;
    const float* pA1 = pA0 + (long)64 * K;
    const float* pB0 = Bm + (n0 + lRow) * K + lCol;
    const float* pB1 = pB0 + (long)64 * K;

    float4 ra0 = *(const float4*)pA0;
    float4 ra1 = *(const float4*)pA1;
    float4 rb0 = *(const float4*)pB0;
    float4 rb1 = *(const float4*)pB1;

    float acc[8][8] = {};

    for (int k0 = 0; k0 < K; k0 += 16) {
        // stage registers -> smem (transposed)
        As[lCol + 0][lRow]      = ra0.x; As[lCol + 1][lRow]      = ra0.y;
        As[lCol + 2][lRow]      = ra0.z; As[lCol + 3][lRow]      = ra0.w;
        As[lCol + 0][lRow + 64] = ra1.x; As[lCol + 1][lRow + 64] = ra1.y;
        As[lCol + 2][lRow + 64] = ra1.z; As[lCol + 3][lRow + 64] = ra1.w;
        Bs[lCol + 0][lRow]      = rb0.x; Bs[lCol + 1][lRow]      = rb0.y;
        Bs[lCol + 2][lRow]      = rb0.z; Bs[lCol + 3][lRow]      = rb0.w;
        Bs[lCol + 0][lRow + 64] = rb1.x; Bs[lCol + 1][lRow + 64] = rb1.y;
        Bs[lCol + 2][lRow + 64] = rb1.z; Bs[lCol + 3][lRow + 64] = rb1.w;
        __syncthreads();

        if (k0 + 16 < K) {
            ra0 = *(const float4*)(pA0 + k0 + 16);
            ra1 = *(const float4*)(pA1 + k0 + 16);
            rb0 = *(const float4*)(pB0 + k0 + 16);
            rb1 = *(const float4*)(pB1 + k0 + 16);
        }

#pragma unroll
        for (int k = 0; k < 16; ++k) {
            const float4 a0 = *(const float4*)&As[k][ty << 2];
            const float4 a1 = *(const float4*)&As[k][64 + (ty << 2)];
            const float4 b0 = *(const float4*)&Bs[k][tx << 2];
            const float4 b1 = *(const float4*)&Bs[k][64 + (tx << 2)];
            float aw[8] = {a0.x, a0.y, a0.z, a0.w, a1.x, a1.y, a1.z, a1.w};
            float bw[8] = {b0.x, b0.y, b0.z, b0.w, b1.x, b1.y, b1.z, b1.w};
#pragma unroll
            for (int i = 0; i < 8; ++i)
#pragma unroll
                for (int j = 0; j < 8; ++j)
                    acc[i][j] = fmaf(aw[i], bw[j], acc[i][j]);
        }
        __syncthreads();
    }

#pragma unroll
    for (int i = 0; i < 8; ++i) {
        const long r = m0 + (ty << 2) + (i & 3) + ((i >= 4) ? 64 : 0);
#pragma unroll
        for (int jh = 0; jh < 2; ++jh) {
            const long c = n0 + (tx << 2) + jh * 64;
            float4 o;
            float* po = &o.x;
#pragma unroll
            for (int j = 0; j < 4; ++j) {
                float val = acc[i][jh * 4 + j];
                if (bias) val += bias[c + j];
                if (DO_TANH) val = tanh_fast(val);
                po[j] = val;
            }
            *(float4*)&C[r * (long)N + c] = o;
        }
    }
}

// ============================================================================
// Fused hidden+logits kernel, 128x128 tiles, 8x8 per thread.
//   A_ROW=false: T[n,a] = sum_q aff[b][q][n] * PB[b][q][a]  (aff read col-wise,
//                which is contiguous since As[k][m] = aff[k][m] directly)
//   A_ROW=true:  T[q,a] = sum_n aff[b][q][n] * PB[b][n][a]  (transpose stage)
//   h = tanh(PAdd + T);  logits[m] = h . Wh + bh
// ============================================================================
template<bool A_ROW>
__global__ __launch_bounds__(256)
void hidden_logits128(const float* __restrict__ aff,
                      const float* __restrict__ PB,    // [K, HA]
                      const float* __restrict__ PAdd,  // [M, HA]
                      const float* __restrict__ Wh,    // [HA]
                      const float* __restrict__ bh,    // [1]
                      float* __restrict__ logits,      // [M] per batch
                      int M, int K, long sPB, long sPAdd)
{
    const int b = blockIdx.z;
    aff    += (long)b * ((long)NQ * NV);
    PB     += (long)b * sPB;
    PAdd   += (long)b * sPAdd;
    logits += (long)b * M;

    __shared__ float As[16][SMPAD];
    __shared__ float Bs[16][SMPAD];

    const int tid = threadIdx.x;
    const int tx = tid & 15, ty = tid >> 4;
    const long m0 = (long)blockIdx.x * 128;

    float acc[8][8] = {};

    // ---- prefetch pointers ----
    // B tile: Bs[k][a] = PB[(k0+k)*HA + a]; thread covers (kk, a4) and (kk+8, a4)
    const int kk = tid >> 5;            // 0..7
    const int a4 = (tid & 31) << 2;     // 0..124
    const float* pBq0 = PB + (long)kk * HA + a4;
    const float* pBq1 = pBq0 + 8 * HA;

    // A tile pointers
    const int lRow = tid >> 2;
    const int lCol = (tid & 3) << 2;
    const float* pAr0;  const float* pAr1;   // A_ROW=true (transpose stage)
    const float* pAc0;  const float* pAc1;   // A_ROW=false (direct stage)
    if (A_ROW) {
        pAr0 = aff + (m0 + lRow) * (long)NV + lCol;
        pAr1 = pAr0 + (long)64 * NV;
        pAc0 = pAc1 = nullptr;
    } else {
        pAc0 = aff + (long)kk * NV + m0 + a4;
        pAc1 = pAc0 + (long)8 * NV;
        pAr0 = pAr1 = nullptr;
    }

    float4 ra0, ra1;
    if (A_ROW) { ra0 = *(const float4*)pAr0; ra1 = *(const float4*)pAr1; }
    else       { ra0 = *(const float4*)pAc0; ra1 = *(const float4*)pAc1; }
    float4 rb0 = *(const float4*)pBq0;
    float4 rb1 = *(const float4*)pBq1;

    for (int k0 = 0; k0 < K; k0 += 16) {
        if (A_ROW) {
            As[lCol + 0][lRow]      = ra0.x; As[lCol + 1][lRow]      = ra0.y;
            As[lCol + 2][lRow]      = ra0.z; As[lCol + 3][lRow]      = ra0.w;
            As[lCol + 0][lRow + 64] = ra1.x; As[lCol + 1][lRow + 64] = ra1.y;
            As[lCol + 2][lRow + 64] = ra1.z; As[lCol + 3][lRow + 64] = ra1.w;
        } else {
            *(float4*)&As[kk][a4]     = ra0;
            *(float4*)&As[kk + 8][a4] = ra1;
        }
        *(float4*)&Bs[kk][a4]     = rb0;
        *(float4*)&Bs[kk + 8][a4] = rb1;
        __syncthreads();

        if (k0 + 16 < K) {
            if (A_ROW) {
                ra0 = *(const float4*)(pAr0 + k0 + 16);
                ra1 = *(const float4*)(pAr1 + k0 + 16);
            } else {
                ra0 = *(const float4*)(pAc0 + (long)(k0 + 16) * NV);
                ra1 = *(const float4*)(pAc1 + (long)(k0 + 16) * NV);
            }
            rb0 = *(const float4*)(pBq0 + (long)(k0 + 16) * HA);
            rb1 = *(const float4*)(pBq1 + (long)(k0 + 16) * HA);
        }

#pragma unroll
        for (int k = 0; k < 16; ++k) {
            const float4 a0 = *(const float4*)&As[k][ty << 2];
            const float4 a1 = *(const float4*)&As[k][64 + (ty << 2)];
            const float4 b0 = *(const float4*)&Bs[k][tx << 2];
            const float4 b1 = *(const float4*)&Bs[k][64 + (tx << 2)];
            float aw[8] = {a0.x, a0.y, a0.z, a0.w, a1.x, a1.y, a1.z, a1.w};
            float bw[8] = {b0.x, b0.y, b0.z, b0.w, b1.x, b1.y, b1.z, b1.w};
#pragma unroll
            for (int i = 0; i < 8; ++i)
#pragma unroll
                for (int j = 0; j < 8; ++j)
                    acc[i][j] = fmaf(aw[i], bw[j], acc[i][j]);
        }
        __syncthreads();
    }

    // ---- epilogue: tanh(PAdd + acc) . Wh, reduce over the 16 tx lanes ----
    const float bhv = *bh;
    float wh[8];
#pragma unroll
    for (int j = 0; j < 4; ++j) {
        wh[j]     = Wh[(tx << 2) + j];
        wh[4 + j] = Wh[64 + (tx << 2) + j];
    }

#pragma unroll
    for (int i = 0; i < 8; ++i) {
        const long r = (ty << 2) + (i & 3) + ((i >= 4) ? 64 : 0);
        const float4 p0 = *(const float4*)&PAdd[(m0 + r) * HA + (tx << 2)];
        const float4 p1 = *(const float4*)&PAdd[(m0 + r) * HA + 64 + (tx << 2)];
        const float pv8[8] = {p0.x, p0.y, p0.z, p0.w, p1.x, p1.y, p1.z, p1.w};
        float partial = 0.f;
#pragma unroll
        for (int j = 0; j < 8; ++j)
            partial = fmaf(wh[j], tanh_fast(pv8[j] + acc[i][j]), partial);
#pragma unroll
        for (int off = 1; off < 16; off <<= 1)
            partial += __shfl_xor_sync(0xffffffffu, partial, off);
        if (tx == 0)
            logits[m0 + r] = partial + bhv;
    }
}

// ============================================================================
// Fused softmax (over sequence axis) + weighted sum of X rows -> out[b][H]
// One block per batch, 256 threads (= H).
// ============================================================================
__global__ __launch_bounds__(256)
void softmax_weighted_kernel(const float* __restrict__ logits,
                             const float* __restrict__ X,
                             float* __restrict__ out, int N)
{
    const int b = blockIdx.x;
    logits += (long)b * N;
    X      += (long)b * N * HH;

    __shared__ float sw[2048];
    __shared__ float red[256];

    const int tid = threadIdx.x;

    float mloc = -1e30f;
    for (int i = tid; i < N; i += 256) {
        float l = logits[i];
        sw[i] = l;
        mloc = fmaxf(mloc, l);
    }
    red[tid] = mloc;
    __syncthreads();
    for (int s = 128; s > 0; s >>= 1) {
        if (tid < s) red[tid] = fmaxf(red[tid], red[tid + s]);
        __syncthreads();
    }
    const float m = red[0];
    __syncthreads();

    float sloc = 0.f;
    for (int i = tid; i < N; i += 256) {
        float e = expf(sw[i] - m);
        sw[i] = e;
        sloc += e;
    }
    red[tid] = sloc;
    __syncthreads();
    for (int s = 128; s > 0; s >>= 1) {
        if (tid < s) red[tid] += red[tid + s];
        __syncthreads();
    }
    const float inv = 1.f / red[0];
    __syncthreads();

    float acc = 0.f;
    const int h = tid;
#pragma unroll 4
    for (int n = 0; n < N; ++n)
        acc = fmaf(sw[n], X[(long)n * HH + h], acc);

    out[(long)b * HH + h] = acc * inv;
}

// ============================================================================
extern "C" void kernel_launch(void* const* d_in, const int* in_sizes, int n_in,
                              void* d_out, int out_size)
{
    const float* v    = (const float*)d_in[0];
    const float* q    = (const float*)d_in[1];
    const float* Waff = (const float*)d_in[2];
    const float* baff = (const float*)d_in[3];
    const float* Wv   = (const float*)d_in[4];
    const float* bv   = (const float*)d_in[5];
    const float* Wq   = (const float*)d_in[6];
    const float* bq   = (const float*)d_in[7];
    const float* Whv  = (const float*)d_in[8];
    const float* bhv  = (const float*)d_in[9];
    const float* Whq  = (const float*)d_in[10];
    const float* bhq  = (const float*)d_in[11];
    float* out = (float*)d_out;

    float *p_va, *p_pv, *p_pq, *p_aff, *p_lv, *p_lq;
    cudaGetSymbolAddress((void**)&p_va,  g_va);
    cudaGetSymbolAddress((void**)&p_pv,  g_pv);
    cudaGetSymbolAddress((void**)&p_pq,  g_pq);
    cudaGetSymbolAddress((void**)&p_aff, g_aff);
    cudaGetSymbolAddress((void**)&p_lv,  g_lv);
    cudaGetSymbolAddress((void**)&p_lq,  g_lq);

    // 1) va = v @ Waff^T + baff   [B*NV, H]
    gemm128_nt<0><<<dim3(HH / 128, (BB * NV) / 128, 1), 256>>>(
        v, Waff, baff, p_va, HH, HH, 0, 0, 0);

    // 2) pv = v @ Wv^T + bv       [B*NV, HA]
    gemm128_nt<0><<<dim3(HA / 128, (BB * NV) / 128, 1), 256>>>(
        v, Wv, bv, p_pv, HA, HH, 0, 0, 0);

    // 3) pq = q @ Wq^T + bq       [B*NQ, HA]
    gemm128_nt<0><<<dim3(HA / 128, (BB * NQ) / 128, 1), 256>>>(
        q, Wq, bq, p_pq, HA, HH, 0, 0, 0);

    // 4) aff[b] = tanh(q[b] @ va[b]^T)   [NQ, NV] per batch
    gemm128_nt<1><<<dim3(NV / 128, NQ / 128, BB), 256>>>(
        q, p_va, nullptr, p_aff, NV, HH,
        (long)NQ * HH, (long)NV * HH, (long)NQ * NV);

    // 5) logits_v[b][n] = Whv . tanh(pv + aff^T @ pq) + bhv
    hidden_logits128<false><<<dim3(NV / 128, 1, BB), 256>>>(
        p_aff, p_pq, p_pv, Whv, bhv, p_lv, NV, NQ,
        (long)NQ * HA, (long)NV * HA);

    // 6) logits_q[b][m] = Whq . tanh(pq + aff @ pv) + bhq
    hidden_logits128<true><<<dim3(NQ / 128, 1, BB), 256>>>(
        p_aff, p_pv, p_pq, Whq, bhq, p_lq, NQ, NV,
        (long)NV * HA, (long)NQ * HA);

    // 7) v_hat = softmax(logits_v) . v   -> out[0 : B*H]
    softmax_weighted_kernel<<<BB, 256>>>(p_lv, v, out, NV);

    // 8) q_hat = softmax(logits_q) . q   -> out[B*H : 2*B*H]
    softmax_weighted_kernel<<<BB, 256>>>(p_lq, q, out + (long)BB * HH, NQ);
}

// round 5
// speedup vs baseline: 1.4515x; 1.4515x over previous
#include <cuda_runtime.h>
#include <cuda_bf16.h>
#include <cstdint>
#include <math.h>

#define BB  64
#define NV  2048
#define NQ  512
#define HH  256
#define HA  128

// ---------------- scratch (device globals; no cudaMalloc allowed) ----------
__device__ float g_va [(size_t)BB * NV * HH];
__device__ float g_pv [(size_t)BB * NV * HA];
__device__ float g_pq [(size_t)BB * NQ * HA];
__device__ float g_aff[(size_t)BB * NQ * NV];
__device__ float g_lv[BB * NV];
__device__ float g_lq[BB * NQ];

#define RSTRIDE 40           // bf16 elems per smem row (32 data + 8 pad) = 80B
#define TILE_B  (128 * RSTRIDE * 2)   // 10240 bytes per tile buffer

// ======================= low-level helpers =================================
__device__ __forceinline__ uint32_t smem_u32(const void* p) {
    uint32_t a;
    asm("{ .reg .u64 t; cvta.to.shared.u64 t, %1; cvt.u32.u64 %0, t; }"
        : "=r"(a) : "l"(p));
    return a;
}
__device__ __forceinline__ void ldsm4(uint32_t* r, uint32_t a) {
    asm volatile("ldmatrix.sync.aligned.m8n8.x4.shared.b16 {%0,%1,%2,%3}, [%4];"
                 : "=r"(r[0]), "=r"(r[1]), "=r"(r[2]), "=r"(r[3]) : "r"(a));
}
__device__ __forceinline__ void mma_bf16(float* c, const uint32_t* a,
                                         const uint32_t* b) {
    asm volatile(
        "mma.sync.aligned.m16n8k16.row.col.f32.bf16.bf16.f32 "
        "{%0,%1,%2,%3}, {%4,%5,%6,%7}, {%8,%9}, {%0,%1,%2,%3};"
        : "+f"(c[0]), "+f"(c[1]), "+f"(c[2]), "+f"(c[3])
        : "r"(a[0]), "r"(a[1]), "r"(a[2]), "r"(a[3]), "r"(b[0]), "r"(b[1]));
}
__device__ __forceinline__ void sts64(uint32_t a, uint32_t x, uint32_t y) {
    asm volatile("st.shared.v2.b32 [%0], {%1,%2};" ::"r"(a), "r"(x), "r"(y) : "memory");
}
__device__ __forceinline__ void st16(uint32_t a, uint16_t v) {
    asm volatile("st.shared.b16 [%0], %1;" ::"r"(a), "h"(v) : "memory");
}
// fp32 -> bf16 hi + bf16 lo (residual), pair-packed (x -> low half)
__device__ __forceinline__ void cvt_split2(float x, float y, uint32_t& hi, uint32_t& lo) {
    uint32_t h;
    asm("cvt.rn.bf16x2.f32 %0, %1, %2;" : "=r"(h) : "f"(y), "f"(x));
    float hx = __uint_as_float(h << 16);
    float hy = __uint_as_float(h & 0xFFFF0000u);
    uint32_t l;
    asm("cvt.rn.bf16x2.f32 %0, %1, %2;" : "=r"(l) : "f"(y - hy), "f"(x - hx));
    hi = h; lo = l;
}
__device__ __forceinline__ void cvt_split1(float x, uint16_t& hi, uint16_t& lo) {
    uint16_t h;
    asm("cvt.rn.bf16.f32 %0, %1;" : "=h"(h) : "f"(x));
    float hf = __uint_as_float((uint32_t)h << 16);
    uint16_t l;
    asm("cvt.rn.bf16.f32 %0, %1;" : "=h"(l) : "f"(x - hf));
    hi = h; lo = l;
}
__device__ __forceinline__ float tanh_fast(float x) {
    float e = __expf(2.0f * x);
    return 1.0f - __fdividef(2.0f, e + 1.0f);
}

// ---- staging: load 16 fp32 per thread for one 128x32 (or 32x128-T) tile ----
template<int TR>
__device__ __forceinline__ void stage_load(const float* __restrict__ X, int ld,
                                           long off, int k0, float* r) {
    const int t = threadIdx.x;
    if (TR) {   // gmem layout [K][M]: rows k, we need smem [m][k]
        const int kq = t >> 3, c = t & 7;
        const float* p = X + (long)(k0 + kq) * ld + off + c;
#pragma unroll
        for (int j = 0; j < 16; ++j) r[j] = p[8 * j];
    } else {    // gmem layout [M][K]
        const int row = t >> 1, kb = ((t & 1) ^ ((t >> 4) & 1)) * 16;
        const float4* p = (const float4*)(X + (off + row) * (long)ld + k0 + kb);
#pragma unroll
        for (int i = 0; i < 4; ++i) {
            float4 v = p[i];
            r[4*i] = v.x; r[4*i+1] = v.y; r[4*i+2] = v.z; r[4*i+3] = v.w;
        }
    }
}
template<int TR>
__device__ __forceinline__ void stage_store(uint32_t sHi, uint32_t sLo,
                                            const float* r) {
    const int t = threadIdx.x;
    if (TR) {
        const int kq = t >> 3, c = t & 7;
#pragma unroll
        for (int j = 0; j < 16; ++j) {
            uint16_t h, l;
            cvt_split1(r[j], h, l);
            const uint32_t a = (uint32_t)(c + 8 * j) * 80 + kq * 2;
            st16(sHi + a, h);
            st16(sLo + a, l);
        }
    } else {
        const int row = t >> 1, kb = ((t & 1) ^ ((t >> 4) & 1)) * 16;
        const uint32_t base = row * 80 + kb * 2;
#pragma unroll
        for (int i = 0; i < 4; ++i) {
            uint32_t h0, l0, h1, l1;
            cvt_split2(r[4*i], r[4*i+1], h0, l0);
            cvt_split2(r[4*i+2], r[4*i+3], h1, l1);
            sts64(sHi + base + 8 * i, h0, h1);
            sts64(sLo + base + 8 * i, l0, l1);
        }
    }
}

// ============================================================================
// mma_gemm: C[M,N] = A?T @ B?T^T via bf16 3-MMA split (m16n8k16 HMMA)
// CTA tile 128x128x32, 8 warps (warp tile 32x64).
// MODE 0: C = acc + bias          MODE 1: C = tanh(acc)
// MODE 2: logits[m] = Wh . tanh(PAdd[m] + acc[m]) + bh   (N = HA = 128)
// TRA/TRB: operand stored [K][dim] in gmem (transpose folded into staging)
// ============================================================================
template<int TRA, int TRB, int MODE>
__global__ __launch_bounds__(256, 1)
void mma_gemm(const float* __restrict__ A, const float* __restrict__ B,
              const float* __restrict__ bias, float* __restrict__ C,
              const float* __restrict__ PAdd, const float* __restrict__ Wh,
              const float* __restrict__ bh, float* __restrict__ logits,
              int K, int lda, int ldb, int ldC,
              long sA, long sB, long sC, long sPAdd, int sLog)
{
    __shared__ __align__(16) unsigned char smem_[4 * TILE_B];
    __shared__ float sPart[2][128];

    const int z = blockIdx.z;
    A += z * sA;  B += z * sB;
    if (MODE < 2) C += z * sC;
    else { PAdd += z * sPAdd; logits += (long)z * sLog; }

    const long m0 = (long)(MODE == 2 ? blockIdx.x : blockIdx.y) * 128;
    const long n0 = (MODE == 2) ? 0 : (long)blockIdx.x * 128;

    const uint32_t sAhi = smem_u32(smem_);
    const uint32_t sAlo = sAhi + TILE_B;
    const uint32_t sBhi = sAlo + TILE_B;
    const uint32_t sBlo = sBhi + TILE_B;

    const int tid = threadIdx.x;
    const int l = tid & 31, wid = tid >> 5;
    const int wm = wid & 3, wn = wid >> 2;

    // ldmatrix lane address components
    const int sub = l >> 3, lr = l & 7;
    const uint32_t aRow = wm * 32 + ((sub & 1) << 3) + lr;   // + mt*16
    const uint32_t aK   = (uint32_t)((sub >> 1) << 3);       // + kt
    const uint32_t bRow = ((sub & 2) << 2) + lr;             // + wn*64 + g*16
    const uint32_t bK   = (uint32_t)((sub & 1) << 3);

    float2 whr[8];
    if (MODE == 2) {
#pragma unroll
        for (int nt = 0; nt < 8; ++nt)
            whr[nt] = *(const float2*)&Wh[wn * 64 + nt * 8 + 2 * (l & 3)];
    }

    float acc[2][8][4] = {};
    float rA[16], rB[16];

    stage_load<TRA>(A, lda, m0, 0, rA);
    stage_load<TRB>(B, ldb, n0, 0, rB);

    const int nchunk = K >> 5;
    for (int ch = 0; ch < nchunk; ++ch) {
        stage_store<TRA>(sAhi, sAlo, rA);
        stage_store<TRB>(sBhi, sBlo, rB);
        __syncthreads();

        if (ch + 1 < nchunk) {
            stage_load<TRA>(A, lda, m0, (ch + 1) * 32, rA);
            stage_load<TRB>(B, ldb, n0, (ch + 1) * 32, rB);
        }

#pragma unroll
        for (int kt = 0; kt < 32; kt += 16) {
            uint32_t Ah[2][4], Al[2][4], Bh[4][4], Bl[4][4];
            const uint32_t ak = (kt + aK) * 2;
#pragma unroll
            for (int mt = 0; mt < 2; ++mt) {
                const uint32_t ra = (aRow + mt * 16) * 80 + ak;
                ldsm4(Ah[mt], sAhi + ra);
                ldsm4(Al[mt], sAlo + ra);
            }
            const uint32_t bk = (kt + bK) * 2;
#pragma unroll
            for (int g = 0; g < 4; ++g) {
                const uint32_t rb = (wn * 64 + g * 16 + bRow) * 80 + bk;
                ldsm4(Bh[g], sBhi + rb);
                ldsm4(Bl[g], sBlo + rb);
            }
#pragma unroll
            for (int mt = 0; mt < 2; ++mt)
#pragma unroll
                for (int g = 0; g < 4; ++g) {
                    mma_bf16(acc[mt][2*g],   Ah[mt], &Bh[g][0]);
                    mma_bf16(acc[mt][2*g+1], Ah[mt], &Bh[g][2]);
                    mma_bf16(acc[mt][2*g],   Ah[mt], &Bl[g][0]);
                    mma_bf16(acc[mt][2*g+1], Ah[mt], &Bl[g][2]);
                    mma_bf16(acc[mt][2*g],   Al[mt], &Bh[g][0]);
                    mma_bf16(acc[mt][2*g+1], Al[mt], &Bh[g][2]);
                }
        }
        __syncthreads();
    }

    // ---------------- epilogue ----------------
    if (MODE < 2) {
#pragma unroll
        for (int mt = 0; mt < 2; ++mt) {
            const long r0 = m0 + wm * 32 + mt * 16 + (l >> 2);
#pragma unroll
            for (int nt = 0; nt < 8; ++nt) {
                const long col = n0 + wn * 64 + nt * 8 + 2 * (l & 3);
                float v0 = acc[mt][nt][0], v1 = acc[mt][nt][1];
                float v2 = acc[mt][nt][2], v3 = acc[mt][nt][3];
                if (MODE == 0) {
                    float2 b2 = *(const float2*)&bias[col];
                    v0 += b2.x; v1 += b2.y; v2 += b2.x; v3 += b2.y;
                } else {
                    v0 = tanh_fast(v0); v1 = tanh_fast(v1);
                    v2 = tanh_fast(v2); v3 = tanh_fast(v3);
                }
                *(float2*)&C[r0 * (long)ldC + col]       = make_float2(v0, v1);
                *(float2*)&C[(r0 + 8) * (long)ldC + col] = make_float2(v2, v3);
            }
        }
    } else {
#pragma unroll
        for (int mt = 0; mt < 2; ++mt) {
            const int rr = wm * 32 + mt * 16 + (l >> 2);
            float s0 = 0.f, s1 = 0.f;
#pragma unroll
            for (int nt = 0; nt < 8; ++nt) {
                const int col = wn * 64 + nt * 8 + 2 * (l & 3);
                const float2 w = whr[nt];
                float2 p0 = *(const float2*)&PAdd[(m0 + rr) * (long)HA + col];
                float2 p1 = *(const float2*)&PAdd[(m0 + rr + 8) * (long)HA + col];
                s0 += w.x * tanh_fast(p0.x + acc[mt][nt][0])
                    + w.y * tanh_fast(p0.y + acc[mt][nt][1]);
                s1 += w.x * tanh_fast(p1.x + acc[mt][nt][2])
                    + w.y * tanh_fast(p1.y + acc[mt][nt][3]);
            }
            s0 += __shfl_xor_sync(0xffffffffu, s0, 1);
            s0 += __shfl_xor_sync(0xffffffffu, s0, 2);
            s1 += __shfl_xor_sync(0xffffffffu, s1, 1);
            s1 += __shfl_xor_sync(0xffffffffu, s1, 2);
            if ((l & 3) == 0) {
                sPart[wn][rr]     = s0;
                sPart[wn][rr + 8] = s1;
            }
        }
        __syncthreads();
        if (tid < 128)
            logits[m0 + tid] = sPart[0][tid] + sPart[1][tid] + bh[0];
    }
}

// ============================================================================
// Fused softmax (sequence axis) + weighted row-sum -> out[b][H]
// ============================================================================
__global__ __launch_bounds__(256)
void softmax_weighted_kernel(const float* __restrict__ logits,
                             const float* __restrict__ X,
                             float* __restrict__ out, int N)
{
    const int b = blockIdx.x;
    logits += (long)b * N;
    X      += (long)b * N * HH;

    __shared__ float sw[2048];
    __shared__ float red[256];
    const int tid = threadIdx.x;

    float mloc = -1e30f;
    for (int i = tid; i < N; i += 256) {
        float v = logits[i];
        sw[i] = v;
        mloc = fmaxf(mloc, v);
    }
    red[tid] = mloc;
    __syncthreads();
    for (int s = 128; s > 0; s >>= 1) {
        if (tid < s) red[tid] = fmaxf(red[tid], red[tid + s]);
        __syncthreads();
    }
    const float m = red[0];
    __syncthreads();

    float sloc = 0.f;
    for (int i = tid; i < N; i += 256) {
        float e = expf(sw[i] - m);
        sw[i] = e;
        sloc += e;
    }
    red[tid] = sloc;
    __syncthreads();
    for (int s = 128; s > 0; s >>= 1) {
        if (tid < s) red[tid] += red[tid + s];
        __syncthreads();
    }
    const float inv = 1.f / red[0];
    __syncthreads();

    float acc = 0.f;
#pragma unroll 4
    for (int n = 0; n < N; ++n)
        acc = fmaf(sw[n], X[(long)n * HH + tid], acc);
    out[(long)b * HH + tid] = acc * inv;
}

// ============================================================================
extern "C" void kernel_launch(void* const* d_in, const int* in_sizes, int n_in,
                              void* d_out, int out_size)
{
    const float* v    = (const float*)d_in[0];
    const float* q    = (const float*)d_in[1];
    const float* Waff = (const float*)d_in[2];
    const float* baff = (const float*)d_in[3];
    const float* Wv   = (const float*)d_in[4];
    const float* bv   = (const float*)d_in[5];
    const float* Wq   = (const float*)d_in[6];
    const float* bq   = (const float*)d_in[7];
    const float* Whv  = (const float*)d_in[8];
    const float* bhv  = (const float*)d_in[9];
    const float* Whq  = (const float*)d_in[10];
    const float* bhq  = (const float*)d_in[11];
    float* out = (float*)d_out;

    float *p_va, *p_pv, *p_pq, *p_aff, *p_lv, *p_lq;
    cudaGetSymbolAddress((void**)&p_va,  g_va);
    cudaGetSymbolAddress((void**)&p_pv,  g_pv);
    cudaGetSymbolAddress((void**)&p_pq,  g_pq);
    cudaGetSymbolAddress((void**)&p_aff, g_aff);
    cudaGetSymbolAddress((void**)&p_lv,  g_lv);
    cudaGetSymbolAddress((void**)&p_lq,  g_lq);

    // 1) va = v @ Waff^T + baff     [B*NV, HH], K=HH
    mma_gemm<0,0,0><<<dim3(HH/128, (BB*NV)/128, 1), 256>>>(
        v, Waff, baff, p_va, nullptr, nullptr, nullptr, nullptr,
        HH, HH, HH, HH, 0, 0, 0, 0, 0);

    // 2) pv = v @ Wv^T + bv         [B*NV, HA]
    mma_gemm<0,0,0><<<dim3(HA/128, (BB*NV)/128, 1), 256>>>(
        v, Wv, bv, p_pv, nullptr, nullptr, nullptr, nullptr,
        HH, HH, HH, HA, 0, 0, 0, 0, 0);

    // 3) pq = q @ Wq^T + bq         [B*NQ, HA]
    mma_gemm<0,0,0><<<dim3(HA/128, (BB*NQ)/128, 1), 256>>>(
        q, Wq, bq, p_pq, nullptr, nullptr, nullptr, nullptr,
        HH, HH, HH, HA, 0, 0, 0, 0, 0);

    // 4) aff[b] = tanh(q[b] @ va[b]^T)   [NQ, NV], K=HH, batched
    mma_gemm<0,0,1><<<dim3(NV/128, NQ/128, BB), 256>>>(
        q, p_va, nullptr, p_aff, nullptr, nullptr, nullptr, nullptr,
        HH, HH, HH, NV, (long)NQ*HH, (long)NV*HH, (long)NQ*NV, 0, 0);

    // 5) logits_v[b][n] = Whv . tanh(pv + aff^T @ pq) + bhv
    //    A = aff^T (TR, lda=NV), B = pq^T (TR, ldb=HA), K=NQ, M=NV
    mma_gemm<1,1,2><<<dim3(NV/128, 1, BB), 256>>>(
        p_aff, p_pq, nullptr, nullptr, p_pv, Whv, bhv, p_lv,
        NQ, NV, HA, 0, (long)NQ*NV, (long)NQ*HA, 0, (long)NV*HA, NV);

    // 6) logits_q[b][m] = Whq . tanh(pq + aff @ pv) + bhq
    //    A = aff (direct, lda=NV), B = pv^T (TR, ldb=HA), K=NV, M=NQ
    mma_gemm<0,1,2><<<dim3(NQ/128, 1, BB), 256>>>(
        p_aff, p_pv, nullptr, nullptr, p_pq, Whq, bhq, p_lq,
        NV, NV, HA, 0, (long)NQ*NV, (long)NV*HA, 0, (long)NQ*HA, NQ);

    // 7) v_hat / q_hat
    softmax_weighted_kernel<<<BB, 256>>>(p_lv, v, out, NV);
    softmax_weighted_kernel<<<BB, 256>>>(p_lq, q, out + (long)BB * HH, NQ);
}

// round 6
// speedup vs baseline: 1.4616x; 1.0070x over previous
#include <cuda_runtime.h>
#include <cuda_bf16.h>
#include <cstdint>
#include <math.h>

#define BB  64
#define NV  2048
#define NQ  512
#define HH  256
#define HA  128

// ---------------- scratch (device globals; no cudaMalloc allowed) ----------
__device__ float g_va [(size_t)BB * NV * HH];
__device__ float g_pv [(size_t)BB * NV * HA];
__device__ float g_pq [(size_t)BB * NQ * HA];
__device__ float g_aff[(size_t)BB * NQ * NV];
__device__ float g_lv[BB * NV];
__device__ float g_lq[BB * NQ];

#define RSTRIDE 40                      // bf16 per smem row (32 data + 8 pad) = 80B
#define TILE_B  (128 * RSTRIDE * 2)     // 10240 bytes per tile buffer
#define BUF_B   (4 * TILE_B)            // Ahi, Alo, Bhi, Blo
#define DYNSMEM (2 * BUF_B)             // double buffered: 81920 bytes

// ======================= low-level helpers =================================
__device__ __forceinline__ uint32_t smem_u32(const void* p) {
    uint32_t a;
    asm("{ .reg .u64 t; cvta.to.shared.u64 t, %1; cvt.u32.u64 %0, t; }"
        : "=r"(a) : "l"(p));
    return a;
}
__device__ __forceinline__ void ldsm4(uint32_t* r, uint32_t a) {
    asm volatile("ldmatrix.sync.aligned.m8n8.x4.shared.b16 {%0,%1,%2,%3}, [%4];"
                 : "=r"(r[0]), "=r"(r[1]), "=r"(r[2]), "=r"(r[3]) : "r"(a));
}
__device__ __forceinline__ void mma_bf16(float* c, const uint32_t* a,
                                         const uint32_t* b) {
    asm volatile(
        "mma.sync.aligned.m16n8k16.row.col.f32.bf16.bf16.f32 "
        "{%0,%1,%2,%3}, {%4,%5,%6,%7}, {%8,%9}, {%0,%1,%2,%3};"
        : "+f"(c[0]), "+f"(c[1]), "+f"(c[2]), "+f"(c[3])
        : "r"(a[0]), "r"(a[1]), "r"(a[2]), "r"(a[3]), "r"(b[0]), "r"(b[1]));
}
__device__ __forceinline__ void sts64(uint32_t a, uint32_t x, uint32_t y) {
    asm volatile("st.shared.v2.b32 [%0], {%1,%2};" ::"r"(a), "r"(x), "r"(y) : "memory");
}
__device__ __forceinline__ void st16(uint32_t a, uint16_t v) {
    asm volatile("st.shared.b16 [%0], %1;" ::"r"(a), "h"(v) : "memory");
}
// fp32 -> bf16 hi + bf16 lo (residual), pair-packed (x -> low half)
__device__ __forceinline__ void cvt_split2(float x, float y, uint32_t& hi, uint32_t& lo) {
    uint32_t h;
    asm("cvt.rn.bf16x2.f32 %0, %1, %2;" : "=r"(h) : "f"(y), "f"(x));
    float hx = __uint_as_float(h << 16);
    float hy = __uint_as_float(h & 0xFFFF0000u);
    uint32_t l;
    asm("cvt.rn.bf16x2.f32 %0, %1, %2;" : "=r"(l) : "f"(y - hy), "f"(x - hx));
    hi = h; lo = l;
}
__device__ __forceinline__ void cvt_split1(float x, uint16_t& hi, uint16_t& lo) {
    uint16_t h;
    asm("cvt.rn.bf16.f32 %0, %1;" : "=h"(h) : "f"(x));
    float hf = __uint_as_float((uint32_t)h << 16);
    uint16_t l;
    asm("cvt.rn.bf16.f32 %0, %1;" : "=h"(l) : "f"(x - hf));
    hi = h; lo = l;
}
__device__ __forceinline__ float tanh_fast(float x) {
    float e = __expf(2.0f * x);
    return 1.0f - __fdividef(2.0f, e + 1.0f);
}

// ---- staging: load 16 fp32 per thread for one 128x32 (or 32x128-T) tile ----
template<int TR>
__device__ __forceinline__ void stage_load(const float* __restrict__ X, int ld,
                                           long off, int k0, float* r) {
    const int t = threadIdx.x;
    if (TR) {   // gmem layout [K][M]: rows k, we need smem [m][k]
        const int kq = t >> 3, c = t & 7;
        const float* p = X + (long)(k0 + kq) * ld + off + c;
#pragma unroll
        for (int j = 0; j < 16; ++j) r[j] = p[8 * j];
    } else {    // gmem layout [M][K]
        const int row = t >> 1, kb = ((t & 1) ^ ((t >> 4) & 1)) * 16;
        const float4* p = (const float4*)(X + (off + row) * (long)ld + k0 + kb);
#pragma unroll
        for (int i = 0; i < 4; ++i) {
            float4 v = p[i];
            r[4*i] = v.x; r[4*i+1] = v.y; r[4*i+2] = v.z; r[4*i+3] = v.w;
        }
    }
}
template<int TR>
__device__ __forceinline__ void stage_store(uint32_t sHi, uint32_t sLo,
                                            const float* r) {
    const int t = threadIdx.x;
    if (TR) {
        const int kq = t >> 3, c = t & 7;
#pragma unroll
        for (int j = 0; j < 16; ++j) {
            uint16_t h, l;
            cvt_split1(r[j], h, l);
            const uint32_t a = (uint32_t)(c + 8 * j) * 80 + kq * 2;
            st16(sHi + a, h);
            st16(sLo + a, l);
        }
    } else {
        const int row = t >> 1, kb = ((t & 1) ^ ((t >> 4) & 1)) * 16;
        const uint32_t base = row * 80 + kb * 2;
#pragma unroll
        for (int i = 0; i < 4; ++i) {
            uint32_t h0, l0, h1, l1;
            cvt_split2(r[4*i], r[4*i+1], h0, l0);
            cvt_split2(r[4*i+2], r[4*i+3], h1, l1);
            sts64(sHi + base + 8 * i, h0, h1);
            sts64(sLo + base + 8 * i, l0, l1);
        }
    }
}

// ============================================================================
// mma_gemm: C[M,N] = A?T @ B?T^T via bf16 3-MMA split (m16n8k16 HMMA)
// CTA tile 128x128x32, 8 warps (warp tile 32x64). Double-buffered smem,
// one __syncthreads per K-chunk.
// MODE 0: C = acc + bias          MODE 1: C = tanh(acc)
// MODE 2: logits[m] = Wh . tanh(PAdd[m] + acc[m]) + bh   (N = HA = 128)
// TRA/TRB: operand stored [K][dim] in gmem (transpose folded into staging)
// ============================================================================
template<int TRA, int TRB, int MODE>
__global__ __launch_bounds__(256, 1)
void mma_gemm(const float* __restrict__ A, const float* __restrict__ B,
              const float* __restrict__ bias, float* __restrict__ C,
              const float* __restrict__ PAdd, const float* __restrict__ Wh,
              const float* __restrict__ bh, float* __restrict__ logits,
              int K, int lda, int ldb, int ldC,
              long sA, long sB, long sC, long sPAdd, int sLog)
{
    extern __shared__ __align__(16) unsigned char smem_[];
    __shared__ float sPart[2][128];

    const int z = blockIdx.z;
    A += z * sA;  B += z * sB;
    if (MODE < 2) C += z * sC;
    else { PAdd += z * sPAdd; logits += (long)z * sLog; }

    const long m0 = (long)(MODE == 2 ? blockIdx.x : blockIdx.y) * 128;
    const long n0 = (MODE == 2) ? 0 : (long)blockIdx.x * 128;

    const uint32_t sb0 = smem_u32(smem_);

    const int tid = threadIdx.x;
    const int l = tid & 31, wid = tid >> 5;
    const int wm = wid & 3, wn = wid >> 2;

    // ldmatrix lane address components
    const int sub = l >> 3, lr = l & 7;
    const uint32_t aRow = wm * 32 + ((sub & 1) << 3) + lr;   // + mt*16
    const uint32_t aK   = (uint32_t)((sub >> 1) << 3);       // + kt
    const uint32_t bRow = ((sub & 2) << 2) + lr;             // + wn*64 + g*16
    const uint32_t bK   = (uint32_t)((sub & 1) << 3);

    float2 whr[8];
    if (MODE == 2) {
#pragma unroll
        for (int nt = 0; nt < 8; ++nt)
            whr[nt] = *(const float2*)&Wh[wn * 64 + nt * 8 + 2 * (l & 3)];
    }

    float acc[2][8][4] = {};
    float rA[16], rB[16];

    // prologue: stage chunk 0 into buffer 0
    stage_load<TRA>(A, lda, m0, 0, rA);
    stage_load<TRB>(B, ldb, n0, 0, rB);
    stage_store<TRA>(sb0, sb0 + TILE_B, rA);
    stage_store<TRB>(sb0 + 2 * TILE_B, sb0 + 3 * TILE_B, rB);
    __syncthreads();

    const int nchunk = K >> 5;
    for (int ch = 0; ch < nchunk; ++ch) {
        const uint32_t cur = sb0 + (ch & 1) * BUF_B;
        const uint32_t nxt = sb0 + ((ch + 1) & 1) * BUF_B;

        // issue global loads for next chunk first (hidden under MMA)
        if (ch + 1 < nchunk) {
            stage_load<TRA>(A, lda, m0, (ch + 1) * 32, rA);
            stage_load<TRB>(B, ldb, n0, (ch + 1) * 32, rB);
        }

        const uint32_t sAhi = cur,               sAlo = cur + TILE_B;
        const uint32_t sBhi = cur + 2 * TILE_B,  sBlo = cur + 3 * TILE_B;

#pragma unroll
        for (int kt = 0; kt < 32; kt += 16) {
            uint32_t Ah[2][4], Al[2][4], Bh[4][4], Bl[4][4];
            const uint32_t ak = (kt + aK) * 2;
#pragma unroll
            for (int mt = 0; mt < 2; ++mt) {
                const uint32_t ra = (aRow + mt * 16) * 80 + ak;
                ldsm4(Ah[mt], sAhi + ra);
                ldsm4(Al[mt], sAlo + ra);
            }
            const uint32_t bk = (kt + bK) * 2;
#pragma unroll
            for (int g = 0; g < 4; ++g) {
                const uint32_t rb = (wn * 64 + g * 16 + bRow) * 80 + bk;
                ldsm4(Bh[g], sBhi + rb);
                ldsm4(Bl[g], sBlo + rb);
            }
#pragma unroll
            for (int mt = 0; mt < 2; ++mt)
#pragma unroll
                for (int g = 0; g < 4; ++g) {
                    mma_bf16(acc[mt][2*g],   Ah[mt], &Bh[g][0]);
                    mma_bf16(acc[mt][2*g+1], Ah[mt], &Bh[g][2]);
                    mma_bf16(acc[mt][2*g],   Ah[mt], &Bl[g][0]);
                    mma_bf16(acc[mt][2*g+1], Ah[mt], &Bl[g][2]);
                    mma_bf16(acc[mt][2*g],   Al[mt], &Bh[g][0]);
                    mma_bf16(acc[mt][2*g+1], Al[mt], &Bh[g][2]);
                }
        }

        // stage next chunk into the other buffer (overlaps others' MMA)
        if (ch + 1 < nchunk) {
            stage_store<TRA>(nxt, nxt + TILE_B, rA);
            stage_store<TRB>(nxt + 2 * TILE_B, nxt + 3 * TILE_B, rB);
        }
        __syncthreads();
    }

    // ---------------- epilogue ----------------
    if (MODE < 2) {
#pragma unroll
        for (int mt = 0; mt < 2; ++mt) {
            const long r0 = m0 + wm * 32 + mt * 16 + (l >> 2);
#pragma unroll
            for (int nt = 0; nt < 8; ++nt) {
                const long col = n0 + wn * 64 + nt * 8 + 2 * (l & 3);
                float v0 = acc[mt][nt][0], v1 = acc[mt][nt][1];
                float v2 = acc[mt][nt][2], v3 = acc[mt][nt][3];
                if (MODE == 0) {
                    float2 b2 = *(const float2*)&bias[col];
                    v0 += b2.x; v1 += b2.y; v2 += b2.x; v3 += b2.y;
                } else {
                    v0 = tanh_fast(v0); v1 = tanh_fast(v1);
                    v2 = tanh_fast(v2); v3 = tanh_fast(v3);
                }
                *(float2*)&C[r0 * (long)ldC + col]       = make_float2(v0, v1);
                *(float2*)&C[(r0 + 8) * (long)ldC + col] = make_float2(v2, v3);
            }
        }
    } else {
#pragma unroll
        for (int mt = 0; mt < 2; ++mt) {
            const int rr = wm * 32 + mt * 16 + (l >> 2);
            float s0 = 0.f, s1 = 0.f;
#pragma unroll
            for (int nt = 0; nt < 8; ++nt) {
                const int col = wn * 64 + nt * 8 + 2 * (l & 3);
                const float2 w = whr[nt];
                float2 p0 = *(const float2*)&PAdd[(m0 + rr) * (long)HA + col];
                float2 p1 = *(const float2*)&PAdd[(m0 + rr + 8) * (long)HA + col];
                s0 += w.x * tanh_fast(p0.x + acc[mt][nt][0])
                    + w.y * tanh_fast(p0.y + acc[mt][nt][1]);
                s1 += w.x * tanh_fast(p1.x + acc[mt][nt][2])
                    + w.y * tanh_fast(p1.y + acc[mt][nt][3]);
            }
            s0 += __shfl_xor_sync(0xffffffffu, s0, 1);
            s0 += __shfl_xor_sync(0xffffffffu, s0, 2);
            s1 += __shfl_xor_sync(0xffffffffu, s1, 1);
            s1 += __shfl_xor_sync(0xffffffffu, s1, 2);
            if ((l & 3) == 0) {
                sPart[wn][rr]     = s0;
                sPart[wn][rr + 8] = s1;
            }
        }
        __syncthreads();
        if (tid < 128)
            logits[m0 + tid] = sPart[0][tid] + sPart[1][tid] + bh[0];
    }
}

// ============================================================================
// Fused softmax (sequence axis) + weighted row-sum -> out[b][H]
// ============================================================================
__global__ __launch_bounds__(256)
void softmax_weighted_kernel(const float* __restrict__ logits,
                             const float* __restrict__ X,
                             float* __restrict__ out, int N)
{
    const int b = blockIdx.x;
    logits += (long)b * N;
    X      += (long)b * N * HH;

    __shared__ float sw[2048];
    __shared__ float red[256];
    const int tid = threadIdx.x;

    float mloc = -1e30f;
    for (int i = tid; i < N; i += 256) {
        float v = logits[i];
        sw[i] = v;
        mloc = fmaxf(mloc, v);
    }
    red[tid] = mloc;
    __syncthreads();
    for (int s = 128; s > 0; s >>= 1) {
        if (tid < s) red[tid] = fmaxf(red[tid], red[tid + s]);
        __syncthreads();
    }
    const float m = red[0];
    __syncthreads();

    float sloc = 0.f;
    for (int i = tid; i < N; i += 256) {
        float e = expf(sw[i] - m);
        sw[i] = e;
        sloc += e;
    }
    red[tid] = sloc;
    __syncthreads();
    for (int s = 128; s > 0; s >>= 1) {
        if (tid < s) red[tid] += red[tid + s];
        __syncthreads();
    }
    const float inv = 1.f / red[0];
    __syncthreads();

    float acc = 0.f;
#pragma unroll 4
    for (int n = 0; n < N; ++n)
        acc = fmaf(sw[n], X[(long)n * HH + tid], acc);
    out[(long)b * HH + tid] = acc * inv;
}

// ============================================================================
extern "C" void kernel_launch(void* const* d_in, const int* in_sizes, int n_in,
                              void* d_out, int out_size)
{
    const float* v    = (const float*)d_in[0];
    const float* q    = (const float*)d_in[1];
    const float* Waff = (const float*)d_in[2];
    const float* baff = (const float*)d_in[3];
    const float* Wv   = (const float*)d_in[4];
    const float* bv   = (const float*)d_in[5];
    const float* Wq   = (const float*)d_in[6];
    const float* bq   = (const float*)d_in[7];
    const float* Whv  = (const float*)d_in[8];
    const float* bhv  = (const float*)d_in[9];
    const float* Whq  = (const float*)d_in[10];
    const float* bhq  = (const float*)d_in[11];
    float* out = (float*)d_out;

    float *p_va, *p_pv, *p_pq, *p_aff, *p_lv, *p_lq;
    cudaGetSymbolAddress((void**)&p_va,  g_va);
    cudaGetSymbolAddress((void**)&p_pv,  g_pv);
    cudaGetSymbolAddress((void**)&p_pq,  g_pq);
    cudaGetSymbolAddress((void**)&p_aff, g_aff);
    cudaGetSymbolAddress((void**)&p_lv,  g_lv);
    cudaGetSymbolAddress((void**)&p_lq,  g_lq);

    cudaFuncSetAttribute(mma_gemm<0,0,0>, cudaFuncAttributeMaxDynamicSharedMemorySize, DYNSMEM);
    cudaFuncSetAttribute(mma_gemm<0,0,1>, cudaFuncAttributeMaxDynamicSharedMemorySize, DYNSMEM);
    cudaFuncSetAttribute(mma_gemm<1,1,2>, cudaFuncAttributeMaxDynamicSharedMemorySize, DYNSMEM);
    cudaFuncSetAttribute(mma_gemm<0,1,2>, cudaFuncAttributeMaxDynamicSharedMemorySize, DYNSMEM);

    // 1) va = v @ Waff^T + baff     [B*NV, HH], K=HH
    mma_gemm<0,0,0><<<dim3(HH/128, (BB*NV)/128, 1), 256, DYNSMEM>>>(
        v, Waff, baff, p_va, nullptr, nullptr, nullptr, nullptr,
        HH, HH, HH, HH, 0, 0, 0, 0, 0);

    // 2) pv = v @ Wv^T + bv         [B*NV, HA]
    mma_gemm<0,0,0><<<dim3(HA/128, (BB*NV)/128, 1), 256, DYNSMEM>>>(
        v, Wv, bv, p_pv, nullptr, nullptr, nullptr, nullptr,
        HH, HH, HH, HA, 0, 0, 0, 0, 0);

    // 3) pq = q @ Wq^T + bq         [B*NQ, HA]
    mma_gemm<0,0,0><<<dim3(HA/128, (BB*NQ)/128, 1), 256, DYNSMEM>>>(
        q, Wq, bq, p_pq, nullptr, nullptr, nullptr, nullptr,
        HH, HH, HH, HA, 0, 0, 0, 0, 0);

    // 4) aff[b] = tanh(q[b] @ va[b]^T)   [NQ, NV], K=HH, batched
    mma_gemm<0,0,1><<<dim3(NV/128, NQ/128, BB), 256, DYNSMEM>>>(
        q, p_va, nullptr, p_aff, nullptr, nullptr, nullptr, nullptr,
        HH, HH, HH, NV, (long)NQ*HH, (long)NV*HH, (long)NQ*NV, 0, 0);

    // 5) logits_v[b][n] = Whv . tanh(pv + aff^T @ pq) + bhv
    mma_gemm<1,1,2><<<dim3(NV/128, 1, BB), 256, DYNSMEM>>>(
        p_aff, p_pq, nullptr, nullptr, p_pv, Whv, bhv, p_lv,
        NQ, NV, HA, 0, (long)NQ*NV, (long)NQ*HA, 0, (long)NV*HA, NV);

    // 6) logits_q[b][m] = Whq . tanh(pq + aff @ pv) + bhq
    mma_gemm<0,1,2><<<dim3(NQ/128, 1, BB), 256, DYNSMEM>>>(
        p_aff, p_pv, nullptr, nullptr, p_pq, Whq, bhq, p_lq,
        NV, NV, HA, 0, (long)NQ*NV, (long)NV*HA, 0, (long)NQ*HA, NQ);

    // 7) v_hat / q_hat
    softmax_weighted_kernel<<<BB, 256>>>(p_lv, v, out, NV);
    softmax_weighted_kernel<<<BB, 256>>>(p_lq, q, out + (long)BB * HH, NQ);
}

// round 7
// speedup vs baseline: 1.5868x; 1.0857x over previous
#include <cuda_runtime.h>
#include <cuda_bf16.h>
#include <cstdint>
#include <math.h>

#define BB  64
#define NV  2048
#define NQ  512
#define HH  256
#define HA  128

typedef __nv_bfloat16 bf16;

// ---------------- scratch (device globals) ---------------------------------
__device__ bf16 g_vhi[(size_t)BB*NV*HH], g_vlo[(size_t)BB*NV*HH];
__device__ bf16 g_qhi[(size_t)BB*NQ*HH], g_qlo[(size_t)BB*NQ*HH];
__device__ bf16 g_Wahi[HH*HH],  g_Walo[HH*HH];
__device__ bf16 g_Wvhi[HA*HH],  g_Wvlo[HA*HH];
__device__ bf16 g_Wqhi[HA*HH],  g_Wqlo[HA*HH];
__device__ bf16 g_vahi[(size_t)BB*NV*HH], g_valo[(size_t)BB*NV*HH];
__device__ float g_pv[(size_t)BB*NV*HA];
__device__ bf16 g_pvThi[(size_t)BB*HA*NV], g_pvTlo[(size_t)BB*HA*NV];
__device__ float g_pq[(size_t)BB*NQ*HA];
__device__ bf16 g_pqThi[(size_t)BB*HA*NQ], g_pqTlo[(size_t)BB*HA*NQ];
__device__ bf16 g_affhi[(size_t)BB*NQ*NV], g_afflo[(size_t)BB*NQ*NV];
__device__ bf16 g_afThi[(size_t)BB*NV*NQ], g_afTlo[(size_t)BB*NV*NQ];
__device__ float g_lv[BB*NV], g_lq[BB*NQ];

#define TILE_B   10240               // 128 rows * 80B
#define BUF_B    (4 * TILE_B)        // Ahi, Alo, Bhi, Blo
#define DYNSMEM  (2 * BUF_B)         // 81920 (double buffer)
#define PLANE_B  33280               // 128*130*2 bounce plane

// ======================= low-level helpers =================================
__device__ __forceinline__ uint32_t smem_u32(const void* p) {
    uint32_t a;
    asm("{ .reg .u64 t; cvta.to.shared.u64 t, %1; cvt.u32.u64 %0, t; }"
        : "=r"(a) : "l"(p));
    return a;
}
__device__ __forceinline__ void ldsm4(uint32_t* r, uint32_t a) {
    asm volatile("ldmatrix.sync.aligned.m8n8.x4.shared.b16 {%0,%1,%2,%3}, [%4];"
                 : "=r"(r[0]), "=r"(r[1]), "=r"(r[2]), "=r"(r[3]) : "r"(a));
}
__device__ __forceinline__ void mma_bf16(float* c, const uint32_t* a,
                                         const uint32_t* b) {
    asm volatile(
        "mma.sync.aligned.m16n8k16.row.col.f32.bf16.bf16.f32 "
        "{%0,%1,%2,%3}, {%4,%5,%6,%7}, {%8,%9}, {%0,%1,%2,%3};"
        : "+f"(c[0]), "+f"(c[1]), "+f"(c[2]), "+f"(c[3])
        : "r"(a[0]), "r"(a[1]), "r"(a[2]), "r"(a[3]), "r"(b[0]), "r"(b[1]));
}
__device__ __forceinline__ void cvt_split2(float x, float y, uint32_t& hi, uint32_t& lo) {
    uint32_t h;
    asm("cvt.rn.bf16x2.f32 %0, %1, %2;" : "=r"(h) : "f"(y), "f"(x));
    float hx = __uint_as_float(h << 16);
    float hy = __uint_as_float(h & 0xFFFF0000u);
    uint32_t l;
    asm("cvt.rn.bf16x2.f32 %0, %1, %2;" : "=r"(l) : "f"(y - hy), "f"(x - hx));
    hi = h; lo = l;
}
__device__ __forceinline__ float tanh_fast(float x) {
    float e = __expf(2.0f * x);
    return 1.0f - __fdividef(2.0f, e + 1.0f);
}

// cp.async stage: 4 tiles (Ahi,Alo,Bhi,Blo), each 128 rows x 64B -> 80B rows
__device__ __forceinline__ void stage_async(uint32_t buf,
        const bf16* __restrict__ Ahi, const bf16* __restrict__ Alo,
        const bf16* __restrict__ Bhi, const bf16* __restrict__ Blo,
        int lda, int ldb, int k0) {
    const int sel = threadIdx.x >> 6;
    const bf16* src = (sel == 0) ? Ahi : (sel == 1) ? Alo : (sel == 2) ? Bhi : Blo;
    const int ld = (sel < 2) ? lda : ldb;
    const int t = threadIdx.x & 63;
    const uint32_t dst = buf + sel * TILE_B;
#pragma unroll
    for (int c = 0; c < 8; ++c) {
        const int lin = c * 64 + t;
        const int row = lin >> 2, qt = lin & 3;
        asm volatile("cp.async.cg.shared.global [%0], [%1], 16;"
            :: "r"(dst + row * 80 + qt * 16),
               "l"((const char*)(src + (long)row * ld + k0) + qt * 16));
    }
}

// write a 128x128 bf16 smem plane (stride 130) to gmem, optional transpose
__device__ __forceinline__ void plane_out(const uint16_t* __restrict__ sm,
                                          bf16* __restrict__ dst,
                                          long row0, long col0, long ld, int tr) {
    const int tid = threadIdx.x;
#pragma unroll
    for (int cI = 0; cI < 8; ++cI) {
        const int g = cI * 256 + tid;
        const int r = g >> 4, ch = g & 15;
        uint16_t e[8];
#pragma unroll
        for (int i = 0; i < 8; ++i)
            e[i] = tr ? sm[(ch * 8 + i) * 130 + r] : sm[r * 130 + ch * 8 + i];
        uint4 w;
        w.x = e[0] | ((uint32_t)e[1] << 16);
        w.y = e[2] | ((uint32_t)e[3] << 16);
        w.z = e[4] | ((uint32_t)e[5] << 16);
        w.w = e[6] | ((uint32_t)e[7] << 16);
        *(uint4*)(dst + (row0 + r) * ld + col0 + ch * 8) = w;
    }
}

// ============================================================================
// split fp32 array -> bf16 hi/lo planes
// ============================================================================
__global__ __launch_bounds__(256)
void split_kernel(const float* __restrict__ x, bf16* __restrict__ hi,
                  bf16* __restrict__ lo, long n)
{
    const long i = ((long)blockIdx.x * 256 + threadIdx.x) * 4;
    if (i >= n) return;
    const float4 v = *(const float4*)(x + i);
    uint32_t h0, l0, h1, l1;
    cvt_split2(v.x, v.y, h0, l0);
    cvt_split2(v.z, v.w, h1, l1);
    *(uint2*)((uint32_t*)hi + (i >> 1)) = make_uint2(h0, h1);
    *(uint2*)((uint32_t*)lo + (i >> 1)) = make_uint2(l0, l1);
}

// ============================================================================
// mma2: C[128-tile] = A @ B^T, bf16 hi/lo pre-split operands, 3-MMA split.
// 128x128x32 CTA tile, 8 warps (32x64), cp.async double buffer, 2 CTA/SM.
// MODE 0: Chi/Clo = split(acc + bias)                       [va]
// MODE 1: Cf = acc + bias (fp32); CThi/lo = transposed split [pv,pq]
// MODE 2: Chi/lo = split(tanh(acc)); CThi/lo transposed      [aff]
// MODE 3: logits[m] = Wh . tanh(PAdd[m] + acc[m]) + bh       [hidden]
// ============================================================================
template<int MODE>
__global__ __launch_bounds__(256, 2)
void mma2(const bf16* __restrict__ Ahi, const bf16* __restrict__ Alo,
          const bf16* __restrict__ Bhi, const bf16* __restrict__ Blo,
          const float* __restrict__ bias,
          bf16* __restrict__ Chi, bf16* __restrict__ Clo,
          bf16* __restrict__ CThi, bf16* __restrict__ CTlo,
          float* __restrict__ Cf,
          const float* __restrict__ PAdd, const float* __restrict__ Wh,
          const float* __restrict__ bh, float* __restrict__ logits,
          int K, int lda, int ldb, int ldC, int ldCT, int rpb,
          long sA, long sB, long sOC, long sOCT, long sPAdd, int sLog)
{
    extern __shared__ __align__(16) unsigned char smem_[];
    __shared__ float sPart[2][128];

    const int z = blockIdx.z;
    Ahi += z * sA;  Alo += z * sA;  Bhi += z * sB;  Blo += z * sB;
    if (MODE == 2) { Chi += z * sOC; Clo += z * sOC; CThi += z * sOCT; CTlo += z * sOCT; }
    if (MODE == 3) { PAdd += z * sPAdd; logits += (long)z * sLog; }

    const long m0 = (long)(MODE == 3 ? blockIdx.x : blockIdx.y) * 128;
    const long n0 = (MODE == 3) ? 0 : (long)blockIdx.x * 128;
    Ahi += m0 * lda;  Alo += m0 * lda;  Bhi += n0 * ldb;  Blo += n0 * ldb;

    const uint32_t sb0 = smem_u32(smem_);
    const int tid = threadIdx.x;
    const int l = tid & 31, wid = tid >> 5;
    const int wm = wid & 3, wn = wid >> 2;

    const int sub = l >> 3, lr = l & 7;
    const uint32_t aRow = wm * 32 + ((sub & 1) << 3) + lr;
    const uint32_t aK   = (uint32_t)((sub >> 1) << 3);
    const uint32_t bRow = ((sub & 2) << 2) + lr;
    const uint32_t bK   = (uint32_t)((sub & 1) << 3);

    float acc[2][8][4] = {};

    stage_async(sb0, Ahi, Alo, Bhi, Blo, lda, ldb, 0);
    asm volatile("cp.async.commit_group;" ::: "memory");

    const int nchunk = K >> 5;
    for (int ch = 0; ch < nchunk; ++ch) {
        if (ch + 1 < nchunk) {
            stage_async(sb0 + ((ch + 1) & 1) * BUF_B, Ahi, Alo, Bhi, Blo,
                        lda, ldb, (ch + 1) * 32);
            asm volatile("cp.async.commit_group;" ::: "memory");
            asm volatile("cp.async.wait_group 1;" ::: "memory");
        } else {
            asm volatile("cp.async.wait_group 0;" ::: "memory");
        }
        __syncthreads();

        const uint32_t cur = sb0 + (ch & 1) * BUF_B;
        const uint32_t sAhi = cur,              sAlo = cur + TILE_B;
        const uint32_t sBhi = cur + 2 * TILE_B, sBlo = cur + 3 * TILE_B;

#pragma unroll
        for (int kt = 0; kt < 32; kt += 16) {
            uint32_t Ah[2][4], Al[2][4], Bh[4][4], Bl[4][4];
            const uint32_t ak = (kt + aK) * 2;
#pragma unroll
            for (int mt = 0; mt < 2; ++mt) {
                const uint32_t ra = (aRow + mt * 16) * 80 + ak;
                ldsm4(Ah[mt], sAhi + ra);
                ldsm4(Al[mt], sAlo + ra);
            }
            const uint32_t bk = (kt + bK) * 2;
#pragma unroll
            for (int g = 0; g < 4; ++g) {
                const uint32_t rb = (wn * 64 + g * 16 + bRow) * 80 + bk;
                ldsm4(Bh[g], sBhi + rb);
                ldsm4(Bl[g], sBlo + rb);
            }
#pragma unroll
            for (int mt = 0; mt < 2; ++mt)
#pragma unroll
                for (int g = 0; g < 4; ++g) {
                    mma_bf16(acc[mt][2*g],   Ah[mt], &Bh[g][0]);
                    mma_bf16(acc[mt][2*g+1], Ah[mt], &Bh[g][2]);
                    mma_bf16(acc[mt][2*g],   Ah[mt], &Bl[g][0]);
                    mma_bf16(acc[mt][2*g+1], Ah[mt], &Bl[g][2]);
                    mma_bf16(acc[mt][2*g],   Al[mt], &Bh[g][0]);
                    mma_bf16(acc[mt][2*g+1], Al[mt], &Bh[g][2]);
                }
        }
        __syncthreads();
    }

    // ---------------- epilogues ----------------
    if (MODE == 0) {
#pragma unroll
        for (int mt = 0; mt < 2; ++mt) {
            const long r0 = m0 + wm * 32 + mt * 16 + (l >> 2);
#pragma unroll
            for (int nt = 0; nt < 8; ++nt) {
                const long col = n0 + wn * 64 + nt * 8 + 2 * (l & 3);
                const float2 b2 = *(const float2*)&bias[col];
                uint32_t h, lo;
                cvt_split2(acc[mt][nt][0] + b2.x, acc[mt][nt][1] + b2.y, h, lo);
                ((uint32_t*)Chi)[(r0 * (long)ldC + col) >> 1] = h;
                ((uint32_t*)Clo)[(r0 * (long)ldC + col) >> 1] = lo;
                cvt_split2(acc[mt][nt][2] + b2.x, acc[mt][nt][3] + b2.y, h, lo);
                ((uint32_t*)Chi)[((r0 + 8) * (long)ldC + col) >> 1] = h;
                ((uint32_t*)Clo)[((r0 + 8) * (long)ldC + col) >> 1] = lo;
            }
        }
    } else if (MODE == 1 || MODE == 2) {
        uint32_t* pHi = (uint32_t*)smem_;
        uint32_t* pLo = (uint32_t*)(smem_ + PLANE_B);
#pragma unroll
        for (int mt = 0; mt < 2; ++mt) {
            const int rl = wm * 32 + mt * 16 + (l >> 2);
#pragma unroll
            for (int nt = 0; nt < 8; ++nt) {
                const int c = wn * 64 + nt * 8 + 2 * (l & 3);
                float v0 = acc[mt][nt][0], v1 = acc[mt][nt][1];
                float v2 = acc[mt][nt][2], v3 = acc[mt][nt][3];
                if (MODE == 1) {
                    const float2 b2 = *(const float2*)&bias[n0 + c];
                    v0 += b2.x; v1 += b2.y; v2 += b2.x; v3 += b2.y;
                    const long r0 = m0 + rl;
                    *(float2*)&Cf[r0 * (long)ldC + n0 + c]       = make_float2(v0, v1);
                    *(float2*)&Cf[(r0 + 8) * (long)ldC + n0 + c] = make_float2(v2, v3);
                } else {
                    v0 = tanh_fast(v0); v1 = tanh_fast(v1);
                    v2 = tanh_fast(v2); v3 = tanh_fast(v3);
                }
                uint32_t h, lo;
                cvt_split2(v0, v1, h, lo);
                pHi[(rl * 130 + c) >> 1] = h;
                pLo[(rl * 130 + c) >> 1] = lo;
                cvt_split2(v2, v3, h, lo);
                pHi[((rl + 8) * 130 + c) >> 1] = h;
                pLo[((rl + 8) * 130 + c) >> 1] = lo;
            }
        }
        __syncthreads();
        const uint16_t* smHi = (const uint16_t*)smem_;
        const uint16_t* smLo = (const uint16_t*)(smem_ + PLANE_B);
        if (MODE == 1) {
            const long b = m0 / rpb, nIn = m0 - b * rpb;
            plane_out(smHi, CThi, b * HA, nIn, ldCT, 1);
            plane_out(smLo, CTlo, b * HA, nIn, ldCT, 1);
        } else {
            plane_out(smHi, Chi,  m0, n0, ldC, 0);
            plane_out(smLo, Clo,  m0, n0, ldC, 0);
            plane_out(smHi, CThi, n0, m0, ldCT, 1);
            plane_out(smLo, CTlo, n0, m0, ldCT, 1);
        }
    } else {  // MODE 3
        float2 whr[8];
#pragma unroll
        for (int nt = 0; nt < 8; ++nt)
            whr[nt] = *(const float2*)&Wh[wn * 64 + nt * 8 + 2 * (l & 3)];
#pragma unroll
        for (int mt = 0; mt < 2; ++mt) {
            const int rr = wm * 32 + mt * 16 + (l >> 2);
            float s0 = 0.f, s1 = 0.f;
#pragma unroll
            for (int nt = 0; nt < 8; ++nt) {
                const int col = wn * 64 + nt * 8 + 2 * (l & 3);
                const float2 w = whr[nt];
                const float2 p0 = *(const float2*)&PAdd[(m0 + rr) * (long)HA + col];
                const float2 p1 = *(const float2*)&PAdd[(m0 + rr + 8) * (long)HA + col];
                s0 += w.x * tanh_fast(p0.x + acc[mt][nt][0])
                    + w.y * tanh_fast(p0.y + acc[mt][nt][1]);
                s1 += w.x * tanh_fast(p1.x + acc[mt][nt][2])
                    + w.y * tanh_fast(p1.y + acc[mt][nt][3]);
            }
            s0 += __shfl_xor_sync(0xffffffffu, s0, 1);
            s0 += __shfl_xor_sync(0xffffffffu, s0, 2);
            s1 += __shfl_xor_sync(0xffffffffu, s1, 1);
            s1 += __shfl_xor_sync(0xffffffffu, s1, 2);
            if ((l & 3) == 0) {
                sPart[wn][rr]     = s0;
                sPart[wn][rr + 8] = s1;
            }
        }
        __syncthreads();
        if (tid < 128)
            logits[m0 + tid] = sPart[0][tid] + sPart[1][tid] + bh[0];
    }
}

// ============================================================================
// Fused softmax (sequence axis) + weighted row-sum -> out[b][H]
// ============================================================================
__global__ __launch_bounds__(256)
void softmax_weighted_kernel(const float* __restrict__ logits,
                             const float* __restrict__ X,
                             float* __restrict__ out, int N)
{
    const int b = blockIdx.x;
    logits += (long)b * N;
    X      += (long)b * N * HH;

    __shared__ float sw[2048];
    __shared__ float red[256];
    const int tid = threadIdx.x;

    float mloc = -1e30f;
    for (int i = tid; i < N; i += 256) {
        float v = logits[i];
        sw[i] = v;
        mloc = fmaxf(mloc, v);
    }
    red[tid] = mloc;
    __syncthreads();
    for (int s = 128; s > 0; s >>= 1) {
        if (tid < s) red[tid] = fmaxf(red[tid], red[tid + s]);
        __syncthreads();
    }
    const float m = red[0];
    __syncthreads();

    float sloc = 0.f;
    for (int i = tid; i < N; i += 256) {
        float e = expf(sw[i] - m);
        sw[i] = e;
        sloc += e;
    }
    red[tid] = sloc;
    __syncthreads();
    for (int s = 128; s > 0; s >>= 1) {
        if (tid < s) red[tid] += red[tid + s];
        __syncthreads();
    }
    const float inv = 1.f / red[0];
    __syncthreads();

    float acc = 0.f;
#pragma unroll 4
    for (int n = 0; n < N; ++n)
        acc = fmaf(sw[n], X[(long)n * HH + tid], acc);
    out[(long)b * HH + tid] = acc * inv;
}

// ============================================================================
extern "C" void kernel_launch(void* const* d_in, const int* in_sizes, int n_in,
                              void* d_out, int out_size)
{
    const float* v    = (const float*)d_in[0];
    const float* q    = (const float*)d_in[1];
    const float* Waff = (const float*)d_in[2];
    const float* baff = (const float*)d_in[3];
    const float* Wv   = (const float*)d_in[4];
    const float* bv   = (const float*)d_in[5];
    const float* Wq   = (const float*)d_in[6];
    const float* bq   = (const float*)d_in[7];
    const float* Whv  = (const float*)d_in[8];
    const float* bhv  = (const float*)d_in[9];
    const float* Whq  = (const float*)d_in[10];
    const float* bhq  = (const float*)d_in[11];
    float* out = (float*)d_out;

    bf16 *vhi, *vlo, *qhi, *qlo, *Wahi, *Walo, *Wvhi, *Wvlo, *Wqhi, *Wqlo;
    bf16 *vahi, *valo, *pvThi, *pvTlo, *pqThi, *pqTlo;
    bf16 *affhi, *afflo, *afThi, *afTlo;
    float *pv, *pq, *lv, *lq;
    cudaGetSymbolAddress((void**)&vhi,  g_vhi);   cudaGetSymbolAddress((void**)&vlo,  g_vlo);
    cudaGetSymbolAddress((void**)&qhi,  g_qhi);   cudaGetSymbolAddress((void**)&qlo,  g_qlo);
    cudaGetSymbolAddress((void**)&Wahi, g_Wahi);  cudaGetSymbolAddress((void**)&Walo, g_Walo);
    cudaGetSymbolAddress((void**)&Wvhi, g_Wvhi);  cudaGetSymbolAddress((void**)&Wvlo, g_Wvlo);
    cudaGetSymbolAddress((void**)&Wqhi, g_Wqhi);  cudaGetSymbolAddress((void**)&Wqlo, g_Wqlo);
    cudaGetSymbolAddress((void**)&vahi, g_vahi);  cudaGetSymbolAddress((void**)&valo, g_valo);
    cudaGetSymbolAddress((void**)&pv,   g_pv);
    cudaGetSymbolAddress((void**)&pvThi, g_pvThi); cudaGetSymbolAddress((void**)&pvTlo, g_pvTlo);
    cudaGetSymbolAddress((void**)&pq,   g_pq);
    cudaGetSymbolAddress((void**)&pqThi, g_pqThi); cudaGetSymbolAddress((void**)&pqTlo, g_pqTlo);
    cudaGetSymbolAddress((void**)&affhi, g_affhi); cudaGetSymbolAddress((void**)&afflo, g_afflo);
    cudaGetSymbolAddress((void**)&afThi, g_afThi); cudaGetSymbolAddress((void**)&afTlo, g_afTlo);
    cudaGetSymbolAddress((void**)&lv, g_lv);       cudaGetSymbolAddress((void**)&lq, g_lq);

    cudaFuncSetAttribute(mma2<0>, cudaFuncAttributeMaxDynamicSharedMemorySize, DYNSMEM);
    cudaFuncSetAttribute(mma2<1>, cudaFuncAttributeMaxDynamicSharedMemorySize, DYNSMEM);
    cudaFuncSetAttribute(mma2<2>, cudaFuncAttributeMaxDynamicSharedMemorySize, DYNSMEM);
    cudaFuncSetAttribute(mma2<3>, cudaFuncAttributeMaxDynamicSharedMemorySize, DYNSMEM);

    // 0) split inputs + weights to bf16 hi/lo
    split_kernel<<<(BB*NV*HH)/1024, 256>>>(v, vhi, vlo, (long)BB*NV*HH);
    split_kernel<<<(BB*NQ*HH)/1024, 256>>>(q, qhi, qlo, (long)BB*NQ*HH);
    split_kernel<<<(HH*HH)/1024, 256>>>(Waff, Wahi, Walo, HH*HH);
    split_kernel<<<(HA*HH)/1024, 256>>>(Wv, Wvhi, Wvlo, HA*HH);
    split_kernel<<<(HA*HH)/1024, 256>>>(Wq, Wqhi, Wqlo, HA*HH);

    // 1) va = split(v @ Waff^T + baff)     [B*NV, HH]
    mma2<0><<<dim3(HH/128, (BB*NV)/128, 1), 256, DYNSMEM>>>(
        vhi, vlo, Wahi, Walo, baff, vahi, valo, nullptr, nullptr, nullptr,
        nullptr, nullptr, nullptr, nullptr,
        HH, HH, HH, HH, 0, 0, 0, 0, 0, 0, 0, 0);

    // 2) pv = v @ Wv^T + bv (fp32) + pvT hi/lo   [B*NV, HA]
    mma2<1><<<dim3(1, (BB*NV)/128, 1), 256, DYNSMEM>>>(
        vhi, vlo, Wvhi, Wvlo, bv, nullptr, nullptr, pvThi, pvTlo, pv,
        nullptr, nullptr, nullptr, nullptr,
        HH, HH, HH, HA, NV, NV, 0, 0, 0, 0, 0, 0);

    // 3) pq = q @ Wq^T + bq (fp32) + pqT hi/lo   [B*NQ, HA]
    mma2<1><<<dim3(1, (BB*NQ)/128, 1), 256, DYNSMEM>>>(
        qhi, qlo, Wqhi, Wqlo, bq, nullptr, nullptr, pqThi, pqTlo, pq,
        nullptr, nullptr, nullptr, nullptr,
        HH, HH, HH, HA, NQ, NQ, 0, 0, 0, 0, 0, 0);

    // 4) aff = split(tanh(q @ va^T)) + affT, per batch
    mma2<2><<<dim3(NV/128, NQ/128, BB), 256, DYNSMEM>>>(
        qhi, qlo, vahi, valo, nullptr, affhi, afflo, afThi, afTlo, nullptr,
        nullptr, nullptr, nullptr, nullptr,
        HH, HH, HH, NV, NQ, 0,
        (long)NQ*HH, (long)NV*HH, (long)NQ*NV, (long)NV*NQ, 0, 0);

    // 5) logits_v = Whv . tanh(pv + affT @ pqT^T) + bhv
    mma2<3><<<dim3(NV/128, 1, BB), 256, DYNSMEM>>>(
        afThi, afTlo, pqThi, pqTlo, nullptr, nullptr, nullptr, nullptr, nullptr,
        nullptr, pv, Whv, bhv, lv,
        NQ, NQ, NQ, 0, 0, 0,
        (long)NV*NQ, (long)HA*NQ, 0, 0, (long)NV*HA, NV);

    // 6) logits_q = Whq . tanh(pq + aff @ pvT^T) + bhq
    mma2<3><<<dim3(NQ/128, 1, BB), 256, DYNSMEM>>>(
        affhi, afflo, pvThi, pvTlo, nullptr, nullptr, nullptr, nullptr, nullptr,
        nullptr, pq, Whq, bhq, lq,
        NV, NV, NV, 0, 0, 0,
        (long)NQ*NV, (long)HA*NV, 0, 0, (long)NQ*HA, NQ);

    // 7) v_hat / q_hat
    softmax_weighted_kernel<<<BB, 256>>>(lv, v, out, NV);
    softmax_weighted_kernel<<<BB, 256>>>(lq, q, out + (long)BB * HH, NQ);
}